// round 5
// baseline (speedup 1.0000x reference)
#include <cuda_runtime.h>
#include <cuda_bf16.h>

// MX quantize-dequantize: block size 32, E8M0 shared scale, E4M3 elements.
// v2: 16 elements/thread as two independent 8-element chunks (4 front-batched
// LDG.128 -> MLP_p1=4), interleaved 4-lane shfl amax reductions, streaming
// (.cs) loads/stores. Scale/quantum math is exact pow2 bit construction.

__device__ __forceinline__ float mx_qdq_elem(float v, float inv_scale, float scale) {
    unsigned sbit = __float_as_uint(v) & 0x80000000u;
    float mag = fabsf(v) * inv_scale;          // exact pow2 multiply
    mag = fminf(mag, 448.0f);                  // E4M3 saturate
    float safe = fmaxf(mag, 0.015625f);        // 2^-6 (subnormal region -> emin)
    int e = (int)(__float_as_uint(safe) >> 23) - 127;
    float quantum = __uint_as_float((unsigned)((e - 3) + 127) << 23); // 2^(e-3)
    float invq    = __uint_as_float((unsigned)((3 - e) + 127) << 23); // 2^(3-e)
    float q = rintf(mag * invq) * quantum * scale; // round-half-even, dequant
    return __uint_as_float(__float_as_uint(q) | sbit);
}

__device__ __forceinline__ float amax8(const float4& a, const float4& b) {
    return fmaxf(fmaxf(fmaxf(fabsf(a.x), fabsf(a.y)), fmaxf(fabsf(a.z), fabsf(a.w))),
                 fmaxf(fmaxf(fabsf(b.x), fabsf(b.y)), fmaxf(fabsf(b.z), fabsf(b.w))));
}

__device__ __forceinline__ void scales_from_amax(float m, float& scale, float& inv_scale) {
    // shared_exp = floor(log2(amax)) - 8, clamped so the pow2 floats stay normal.
    // amax==0 -> all elements zero -> scale irrelevant.
    int se = ((int)(__float_as_uint(m) >> 23) - 127) - 8;
    se = max(se, -126);
    scale     = __uint_as_float((unsigned)(se + 127) << 23);
    inv_scale = __uint_as_float((unsigned)(127 - se) << 23);
}

__device__ __forceinline__ float4 qdq4(const float4& a, float inv_scale, float scale) {
    float4 o;
    o.x = mx_qdq_elem(a.x, inv_scale, scale);
    o.y = mx_qdq_elem(a.y, inv_scale, scale);
    o.z = mx_qdq_elem(a.z, inv_scale, scale);
    o.w = mx_qdq_elem(a.w, inv_scale, scale);
    return o;
}

__global__ void __launch_bounds__(256)
mx_qdq_kernel(const float4* __restrict__ x, float4* __restrict__ y,
              int nvec, int stride_vec) {
    int t  = blockIdx.x * blockDim.x + threadIdx.x;
    int i0 = t * 2;               // chunk A: float4 pair
    int i1 = i0 + stride_vec;     // chunk B: float4 pair (independent 32-block set)
    if (i1 + 1 >= nvec) {
        // tail safety (not hit for 4096x8192, but keep it correct generally)
        if (i0 + 1 < nvec) {
            float4 a0 = __ldcs(&x[i0]);
            float4 a1 = __ldcs(&x[i0 + 1]);
            float m = amax8(a0, a1);
            m = fmaxf(m, __shfl_xor_sync(0xffffffffu, m, 1));
            m = fmaxf(m, __shfl_xor_sync(0xffffffffu, m, 2));
            float s, is; scales_from_amax(m, s, is);
            __stcs(&y[i0],     qdq4(a0, is, s));
            __stcs(&y[i0 + 1], qdq4(a1, is, s));
        }
        return;
    }

    // Front-batch all 4 loads: MLP_p1 = 4
    float4 a0 = __ldcs(&x[i0]);
    float4 a1 = __ldcs(&x[i0 + 1]);
    float4 b0 = __ldcs(&x[i1]);
    float4 b1 = __ldcs(&x[i1 + 1]);

    float mA = amax8(a0, a1);
    float mB = amax8(b0, b1);

    // Interleave the two 4-lane reductions so SHFL latency overlaps
    float mA1 = __shfl_xor_sync(0xffffffffu, mA, 1);
    float mB1 = __shfl_xor_sync(0xffffffffu, mB, 1);
    mA = fmaxf(mA, mA1);
    mB = fmaxf(mB, mB1);
    float mA2 = __shfl_xor_sync(0xffffffffu, mA, 2);
    float mB2 = __shfl_xor_sync(0xffffffffu, mB, 2);
    mA = fmaxf(mA, mA2);
    mB = fmaxf(mB, mB2);

    float sA, isA, sB, isB;
    scales_from_amax(mA, sA, isA);
    scales_from_amax(mB, sB, isB);

    __stcs(&y[i0],     qdq4(a0, isA, sA));
    __stcs(&y[i0 + 1], qdq4(a1, isA, sA));
    __stcs(&y[i1],     qdq4(b0, isB, sB));
    __stcs(&y[i1 + 1], qdq4(b1, isB, sB));
}

extern "C" void kernel_launch(void* const* d_in, const int* in_sizes, int n_in,
                              void* d_out, int out_size) {
    const float* x = (const float*)d_in[0];
    float*       y = (float*)d_out;
    int n    = in_sizes[0];        // 33,554,432 (divisible by 32)
    int nvec = n / 4;              // 8,388,608 float4
    int nthreads = nvec / 4;       // 16 elements per thread -> 2,097,152 threads
    int stride_vec = nthreads * 2; // float4 offset between chunk A and chunk B
    int block = 256;
    int grid  = (nthreads + block - 1) / block;  // 8192
    mx_qdq_kernel<<<grid, block>>>((const float4*)x, (float4*)y, nvec, stride_vec);
}